// round 13
// baseline (speedup 1.0000x reference)
#include <cuda_runtime.h>
#include <cuda_bf16.h>
#include <cstdint>

#define BATCH 32
#define NDIM  768
#define MTOT  (BATCH * NDIM)     // 24576
#define BK    32
#define NKT3  (NDIM / BK)        // 24 tf32 chunks (X @ W_l)
#define NKT_T (NKT3 + NDIM / BK) // 36 total (+12 bf16 chunks Y @ W_l1)

typedef __nv_bfloat16 bf16;

// ---------------------------------------------------------------------------
// Scratch
// ---------------------------------------------------------------------------
#define NF_K   (NDIM / 8)                 // 96
#define NF_M   (MTOT / 16)                // 1536
__device__ uint32_t g_Xt[(size_t)NF_M * NF_K * 128];  // X tf32, A-fragment-packed
__device__ uint32_t g_Wt[(size_t)NF_K * NF_K * 64];   // W_l tf32, B-fragment-packed
__device__ bf16 g_Xhi[(size_t)MTOT * NDIM];           // bf16(X)
__device__ bf16 g_Wl1_hi[(size_t)NDIM * NDIM];
__device__ bf16 g_Adj[(size_t)BATCH * NDIM * NDIM];
__device__ bf16 g_Y [(size_t)MTOT * NDIM];            // adj_n @ Xhi

// ---------------------------------------------------------------------------
// smem geometry — CTA tile is now 256(m) x 128(n)
// ---------------------------------------------------------------------------
#define APAD 40
#define BPAD 136
#define A_BYTES (256 * APAD * 2)          // 20480 (256-row A tile)
#define B_BYTES (BK * BPAD * 2)           // 8704

// aggx: 3 stages of (A 256x32 bf16 + B 32x128 bf16)
#define S1_AHI 0
#define S1_BHI (A_BYTES)
#define S1_BYTES (A_BYTES + B_BYTES)      // 29184
#define SMEM1T (3 * S1_BYTES)             // 87552 -> 1 CTA/SM

// biggemm: 3 stages x 48KB. tf32 chunk: A-pack 32KB @0, B-pack 16KB @32768.
//          bf16 chunk: A (APAD) @0, B (BPAD) @32768.
#define SBG   49152
#define SBG_B 32768
#define SMEM_BG (3 * SBG)                 // 147456 -> 1 CTA/SM

// ---------------------------------------------------------------------------
// PTX helpers
// ---------------------------------------------------------------------------
__device__ __forceinline__ uint32_t smem_u32(const void* p) {
    uint32_t a;
    asm("{ .reg .u64 t; cvta.to.shared.u64 t, %1; cvt.u32.u64 %0, t; }" : "=r"(a) : "l"(p));
    return a;
}
__device__ __forceinline__ void ldsm4(uint32_t* r, uint32_t addr) {
    asm volatile("ldmatrix.sync.aligned.m8n8.x4.shared.b16 {%0,%1,%2,%3}, [%4];"
                 : "=r"(r[0]), "=r"(r[1]), "=r"(r[2]), "=r"(r[3]) : "r"(addr));
}
__device__ __forceinline__ void ldsm4t(uint32_t* r, uint32_t addr) {
    asm volatile("ldmatrix.sync.aligned.m8n8.x4.trans.shared.b16 {%0,%1,%2,%3}, [%4];"
                 : "=r"(r[0]), "=r"(r[1]), "=r"(r[2]), "=r"(r[3]) : "r"(addr));
}
__device__ __forceinline__ void lds128(uint32_t* r, uint32_t addr) {
    asm volatile("ld.shared.v4.b32 {%0,%1,%2,%3}, [%4];"
                 : "=r"(r[0]), "=r"(r[1]), "=r"(r[2]), "=r"(r[3]) : "r"(addr));
}
__device__ __forceinline__ void lds64(uint32_t* r, uint32_t addr) {
    asm volatile("ld.shared.v2.b32 {%0,%1}, [%2];" : "=r"(r[0]), "=r"(r[1]) : "r"(addr));
}
__device__ __forceinline__ void hmma(float* d, const uint32_t* a, const uint32_t* b) {
    asm volatile("mma.sync.aligned.m16n8k16.row.col.f32.bf16.bf16.f32 "
                 "{%0,%1,%2,%3}, {%4,%5,%6,%7}, {%8,%9}, {%0,%1,%2,%3};"
                 : "+f"(d[0]), "+f"(d[1]), "+f"(d[2]), "+f"(d[3])
                 : "r"(a[0]), "r"(a[1]), "r"(a[2]), "r"(a[3]), "r"(b[0]), "r"(b[1]));
}
__device__ __forceinline__ void mma_tf32(float* d, const uint32_t* a, const uint32_t* b) {
    asm volatile("mma.sync.aligned.m16n8k8.row.col.f32.tf32.tf32.f32 "
                 "{%0,%1,%2,%3}, {%4,%5,%6,%7}, {%8,%9}, {%0,%1,%2,%3};"
                 : "+f"(d[0]), "+f"(d[1]), "+f"(d[2]), "+f"(d[3])
                 : "r"(a[0]), "r"(a[1]), "r"(a[2]), "r"(a[3]), "r"(b[0]), "r"(b[1]));
}
__device__ __forceinline__ uint32_t f2tf32(float x) {
    uint32_t r;
    asm("cvt.rna.tf32.f32 %0, %1;" : "=r"(r) : "f"(x));
    return r;
}
__device__ __forceinline__ void cp16(uint32_t dst, const void* src) {
    asm volatile("cp.async.cg.shared.global [%0], [%1], 16;" :: "r"(dst), "l"(src));
}
#define CP_COMMIT() asm volatile("cp.async.commit_group;" ::: "memory")
#define CP_WAIT1()  asm volatile("cp.async.wait_group 1;" ::: "memory")

// ---------------- prep (unchanged, proven) ----------------
__global__ __launch_bounds__(192)
void adjprep_kernel(const float* __restrict__ adj) {
    int row = blockIdx.x;
    int t   = threadIdx.x;
    const float4 v = ((const float4*)(adj + (size_t)row * NDIM))[t];
    float s = v.x + v.y + v.z + v.w;
    __shared__ float ws[6];
    __shared__ float rsh;
#pragma unroll
    for (int o = 16; o > 0; o >>= 1) s += __shfl_down_sync(0xffffffffu, s, o);
    if ((t & 31) == 0) ws[t >> 5] = s;
    __syncthreads();
    if (t == 0) {
        float tot = ws[0] + ws[1] + ws[2] + ws[3] + ws[4] + ws[5];
        rsh = (tot == 0.f) ? 0.f : (1.f / tot);
    }
    __syncthreads();
    float r = rsh;
    size_t base = (size_t)row * NDIM + t * 4;
    ((__nv_bfloat162*)(g_Adj + base))[0] =
        __nv_bfloat162(__float2bfloat16(v.x * r), __float2bfloat16(v.y * r));
    ((__nv_bfloat162*)(g_Adj + base))[1] =
        __nv_bfloat162(__float2bfloat16(v.z * r), __float2bfloat16(v.w * r));
}

__global__ __launch_bounds__(256)
void xhi_kernel(const float* __restrict__ X) {
    size_t i = ((size_t)blockIdx.x * 256 + threadIdx.x) * 4;
    float4 v = *(const float4*)(X + i);
    ((__nv_bfloat162*)(g_Xhi + i))[0] =
        __nv_bfloat162(__float2bfloat16(v.x), __float2bfloat16(v.y));
    ((__nv_bfloat162*)(g_Xhi + i))[1] =
        __nv_bfloat162(__float2bfloat16(v.z), __float2bfloat16(v.w));
}

__global__ __launch_bounds__(256)
void xpack_kernel(const float* __restrict__ X) {
    int fg   = blockIdx.x * 8 + (threadIdx.x >> 5);
    int lane = threadIdx.x & 31;
    int m16 = fg / NF_K, k8 = fg % NF_K;
    int g = lane >> 2, c = lane & 3;
    const float* b = X + (size_t)(m16 * 16 + g) * NDIM + k8 * 8 + c;
    uint4 o;
    o.x = f2tf32(b[0]);
    o.y = f2tf32(b[8 * NDIM]);
    o.z = f2tf32(b[4]);
    o.w = f2tf32(b[8 * NDIM + 4]);
    ((uint4*)(g_Xt + (size_t)fg * 128))[lane] = o;
}

__global__ __launch_bounds__(256)
void wpack_kernel(const float* __restrict__ W_l) {
    int fg   = blockIdx.x * 8 + (threadIdx.x >> 5);
    int lane = threadIdx.x & 31;
    int k8 = fg / NF_K, n8 = fg % NF_K;
    int g = lane >> 2, c = lane & 3;
    uint2 o;
    o.x = f2tf32(W_l[(size_t)(k8 * 8 + c) * NDIM + n8 * 8 + g]);
    o.y = f2tf32(W_l[(size_t)(k8 * 8 + c + 4) * NDIM + n8 * 8 + g]);
    ((uint2*)(g_Wt + (size_t)fg * 64))[lane] = o;
}

__global__ __launch_bounds__(256)
void w1hi_kernel(const float* __restrict__ W_l1) {
    size_t i = ((size_t)blockIdx.x * 256 + threadIdx.x) * 4;
    float4 v = *(const float4*)(W_l1 + i);
    ((__nv_bfloat162*)(g_Wl1_hi + i))[0] =
        __nv_bfloat162(__float2bfloat16(v.x), __float2bfloat16(v.y));
    ((__nv_bfloat162*)(g_Wl1_hi + i))[1] =
        __nv_bfloat162(__float2bfloat16(v.z), __float2bfloat16(v.w));
}

// ---------------------------------------------------------------------------
// aggx: Y = adj_n @ Xhi.  CTA 256x128, warp tile 64x64 (4m x 2n), 1 CTA/SM.
// grid (6, 3, 32)
// ---------------------------------------------------------------------------
__global__ __launch_bounds__(256, 1)
void aggx_kernel() {
    extern __shared__ char sm[];
    const uint32_t smb = smem_u32(sm);

    const int b  = blockIdx.z;
    const int nb = blockIdx.x * 128;
    const int mb = blockIdx.y * 256;
    const size_t bo = (size_t)b * NDIM * NDIM;
    const bf16* A = g_Adj + bo;
    const bf16* B = g_Xhi + bo;

    const int tid  = threadIdx.x;
    const int lane = tid & 31;
    const int wid  = tid >> 5;
    const int wm   = wid >> 1;          // 0..3 -> 64-row band
    const int wn   = wid & 1;           // 0..1 -> 64-col band

    // cp mapping: A: thread t = row (256), 4x16B per row; B: bkr=t>>3, 2x16B
    const int bkr = tid >> 3;
    const int bnc = (tid & 7) * 2;

    auto issue = [&](int kt) {
        const uint32_t st = smb + (kt % 3) * S1_BYTES;
        const size_t asrc = (size_t)(mb + tid) * NDIM + kt * BK;
        const size_t bsrc = (size_t)(kt * BK + bkr) * NDIM + nb;
#pragma unroll
        for (int c = 0; c < 4; c++)
            cp16(st + S1_AHI + (uint32_t)(tid * APAD + c * 8) * 2, A + asrc + c * 8);
#pragma unroll
        for (int c = 0; c < 2; c++) {
            int no = (bnc + c) * 8;
            cp16(st + S1_BHI + (uint32_t)(bkr * BPAD + no) * 2, B + bsrc + no);
        }
        CP_COMMIT();
    };

    float acc[4][8][4];
#pragma unroll
    for (int i = 0; i < 4; i++)
#pragma unroll
        for (int j = 0; j < 8; j++)
#pragma unroll
            for (int q = 0; q < 4; q++) acc[i][j][q] = 0.f;

    issue(0);
    issue(1);

#pragma unroll 1
    for (int kt = 0; kt < NKT3; kt++) {
        CP_WAIT1();
        __syncthreads();
        if (kt + 2 < NKT3) issue(kt + 2); else CP_COMMIT();

        const uint32_t st = smb + (kt % 3) * S1_BYTES;
#pragma unroll
        for (int ks = 0; ks < 2; ks++) {
            const int k0 = ks * 16;
            uint32_t ahi[4][4], bhi[4][4];
#pragma unroll
            for (int m = 0; m < 4; m++)
                ldsm4(ahi[m], st + S1_AHI + (uint32_t)((wm * 64 + m * 16 + (lane & 15)) * APAD
                                                       + k0 + (lane >> 4) * 8) * 2);
#pragma unroll
            for (int p = 0; p < 4; p++)
                ldsm4t(bhi[p], st + S1_BHI + (uint32_t)((k0 + (lane & 15)) * BPAD
                                                        + wn * 64 + p * 16 + (lane >> 4) * 8) * 2);
#pragma unroll
            for (int m = 0; m < 4; m++)
#pragma unroll
                for (int p = 0; p < 4; p++)
#pragma unroll
                    for (int h = 0; h < 2; h++)
                        hmma(acc[m][p * 2 + h], ahi[m], &bhi[p][h * 2]);
        }
    }

    const int row0 = mb + wm * 64 + (lane >> 2);
    const int col0 = nb + wn * 64 + (lane & 3) * 2;
#pragma unroll
    for (int m = 0; m < 4; m++)
#pragma unroll
        for (int ns = 0; ns < 8; ns++) {
            bf16* c0 = g_Y + bo + (size_t)(row0 + m * 16) * NDIM + col0 + ns * 8;
            bf16* c1 = c0 + 8 * NDIM;
            *(__nv_bfloat162*)c0 = __nv_bfloat162(
                __float2bfloat16(acc[m][ns][0]), __float2bfloat16(acc[m][ns][1]));
            *(__nv_bfloat162*)c1 = __nv_bfloat162(
                __float2bfloat16(acc[m][ns][2]), __float2bfloat16(acc[m][ns][3]));
        }
}

// ---------------------------------------------------------------------------
// biggemm: out = lrelu( X@W_l (tf32) + Y@W_l1 (bf16) ).
// CTA 256x128, warp tile 64x64, 1 CTA/SM.  grid (6, 96)
// ---------------------------------------------------------------------------
__global__ __launch_bounds__(256, 1)
void biggemm_kernel(float* __restrict__ out) {
    extern __shared__ char sm[];
    const uint32_t smb = smem_u32(sm);

    const int nb = blockIdx.x * 128;
    const int mb = blockIdx.y * 256;
    const int tid  = threadIdx.x;
    const int lane = tid & 31;
    const int wid  = tid >> 5;
    const int wm   = wid >> 1;
    const int wn   = wid & 1;

    const int bkr = tid >> 3;
    const int bnc = (tid & 7) * 2;

    auto issue = [&](int kt) {
        const uint32_t st = smb + (kt % 3) * SBG;
        if (kt < NKT3) {
            // A: 16 m16-frags x 4 k8-frags = 32KB; slab per m16l = 2KB contiguous
            const int m16l = tid >> 4;                    // 0..15
            const int tin  = tid & 15;
            const uint32_t* asrc = g_Xt + ((size_t)(mb / 16 + m16l) * NF_K + kt * 4) * 128;
            uint32_t adst = st + m16l * 2048;
#pragma unroll
            for (int c = 0; c < 8; c++) {
                uint32_t off = (uint32_t)(c * 16 + tin) * 16;
                cp16(adst + off, (const char*)asrc + off);
            }
            // B: 4 k8 x 16 n8 = 16KB; slab per k8l = 4KB contiguous
            const int k8l = tid >> 6;
            const uint32_t* bsrc = g_Wt + ((size_t)(kt * 4 + k8l) * NF_K + nb / 8) * 64;
            uint32_t bdst = st + SBG_B + k8l * 4096;
            const int t64 = tid & 63;
#pragma unroll
            for (int c = 0; c < 4; c++) {
                uint32_t off = (uint32_t)(c * 64 + t64) * 16;
                cp16(bdst + off, (const char*)bsrc + off);
            }
        } else {
            const int k2 = kt - NKT3;
            const size_t asrc = (size_t)(mb + tid) * NDIM + k2 * BK;
            const size_t bsrc = (size_t)(k2 * BK + bkr) * NDIM + nb;
#pragma unroll
            for (int c = 0; c < 4; c++)
                cp16(st + (uint32_t)(tid * APAD + c * 8) * 2, g_Y + asrc + c * 8);
#pragma unroll
            for (int c = 0; c < 2; c++) {
                int no = (bnc + c) * 8;
                cp16(st + SBG_B + (uint32_t)(bkr * BPAD + no) * 2, g_Wl1_hi + bsrc + no);
            }
        }
        CP_COMMIT();
    };

    float acc[4][8][4];
#pragma unroll
    for (int i = 0; i < 4; i++)
#pragma unroll
        for (int j = 0; j < 8; j++)
#pragma unroll
            for (int q = 0; q < 4; q++) acc[i][j][q] = 0.f;

    issue(0);
    issue(1);

#pragma unroll 1
    for (int kt = 0; kt < NKT_T; kt++) {
        CP_WAIT1();
        __syncthreads();
        if (kt + 2 < NKT_T) issue(kt + 2); else CP_COMMIT();

        const uint32_t st = smb + (kt % 3) * SBG;
        if (kt < NKT3) {
            // tf32: 4 k8 slices; per slice 4 A-frags x 8 B-frags = 32 mma
#pragma unroll
            for (int ks = 0; ks < 4; ks++) {
                uint32_t a[4][4];
#pragma unroll
                for (int m = 0; m < 4; m++)
                    lds128(a[m], st + (uint32_t)(((wm * 4 + m) * 4 + ks) * 512 + lane * 16));
                uint32_t b[8][2];
#pragma unroll
                for (int ns = 0; ns < 8; ns++)
                    lds64(b[ns], st + SBG_B + (uint32_t)((ks * 16 + wn * 8 + ns) * 256 + lane * 8));
#pragma unroll
                for (int m = 0; m < 4; m++)
#pragma unroll
                    for (int ns = 0; ns < 8; ns++)
                        mma_tf32(acc[m][ns], a[m], b[ns]);
            }
        } else {
#pragma unroll
            for (int ks = 0; ks < 2; ks++) {
                const int k0 = ks * 16;
                uint32_t ahi[4][4], bhi[4][4];
#pragma unroll
                for (int m = 0; m < 4; m++)
                    ldsm4(ahi[m], st + (uint32_t)((wm * 64 + m * 16 + (lane & 15)) * APAD
                                                  + k0 + (lane >> 4) * 8) * 2);
#pragma unroll
                for (int p = 0; p < 4; p++)
                    ldsm4t(bhi[p], st + SBG_B + (uint32_t)((k0 + (lane & 15)) * BPAD
                                                           + wn * 64 + p * 16 + (lane >> 4) * 8) * 2);
#pragma unroll
                for (int m = 0; m < 4; m++)
#pragma unroll
                    for (int p = 0; p < 4; p++)
#pragma unroll
                        for (int h = 0; h < 2; h++)
                            hmma(acc[m][p * 2 + h], ahi[m], &bhi[p][h * 2]);
            }
        }
    }

    const int row0 = mb + wm * 64 + (lane >> 2);
    const int col0 = nb + wn * 64 + (lane & 3) * 2;
#pragma unroll
    for (int m = 0; m < 4; m++)
#pragma unroll
        for (int ns = 0; ns < 8; ns++) {
            float h0 = acc[m][ns][0], h1 = acc[m][ns][1];
            float h2 = acc[m][ns][2], h3 = acc[m][ns][3];
            h0 = (h0 > 0.f) ? h0 : 0.01f * h0;
            h1 = (h1 > 0.f) ? h1 : 0.01f * h1;
            h2 = (h2 > 0.f) ? h2 : 0.01f * h2;
            h3 = (h3 > 0.f) ? h3 : 0.01f * h3;
            float* c0 = out + (size_t)(row0 + m * 16) * NDIM + col0 + ns * 8;
            float* c1 = c0 + 8 * NDIM;
            *(float2*)c0 = make_float2(h0, h1);
            *(float2*)c1 = make_float2(h2, h3);
        }
}

// ---------------------------------------------------------------------------
extern "C" void kernel_launch(void* const* d_in, const int* in_sizes, int n_in,
                              void* d_out, int out_size)
{
    const float* X    = (const float*)d_in[0];
    const float* adj  = (const float*)d_in[1];
    const float* W_l  = (const float*)d_in[2];
    const float* W_l1 = (const float*)d_in[3];
    float* out = (float*)d_out;

    cudaFuncSetAttribute(aggx_kernel,    cudaFuncAttributeMaxDynamicSharedMemorySize, SMEM1T);
    cudaFuncSetAttribute(biggemm_kernel, cudaFuncAttributeMaxDynamicSharedMemorySize, SMEM_BG);

    adjprep_kernel<<<MTOT, 192>>>(adj);
    xhi_kernel<<<(MTOT * NDIM) / 1024, 256>>>(X);
    xpack_kernel<<<(NF_M * NF_K) / 8, 256>>>(X);
    wpack_kernel<<<(NF_K * NF_K) / 8, 256>>>(W_l);
    w1hi_kernel<<<(NDIM * NDIM) / 1024, 256>>>(W_l1);

    aggx_kernel<<<dim3(6, 3, 32), 256, SMEM1T>>>();
    biggemm_kernel<<<dim3(6, 96), 256, SMEM_BG>>>(out);
}

// round 14
// speedup vs baseline: 1.3838x; 1.3838x over previous
#include <cuda_runtime.h>
#include <cuda_fp16.h>
#include <cstdint>

#define BATCH 32
#define NDIM  768
#define MTOT  (BATCH * NDIM)     // 24576
#define BK    32
#define NKT1  (NDIM / BK)        // 24 (aggx)
#define NKT_T (2 * NDIM / BK)    // 36... no: 1536/32 = 48
#undef NKT_T
#define NKT_T (1536 / BK)        // 48 chunks for biggemm (K=1536)
#define SXY   1536               // row stride of [X | Y]

// ---------------------------------------------------------------------------
// Scratch (all fp16)
// ---------------------------------------------------------------------------
__device__ __half g_XY  [(size_t)MTOT * SXY];          // [X | Y] per row
__device__ __half g_Wcat[(size_t)1536 * NDIM];         // [W_l ; W_l1], rows = k
__device__ __half g_Adj [(size_t)BATCH * NDIM * NDIM]; // adj * rinv

// ---------------------------------------------------------------------------
// smem geometry (identical to R7-proven)
// ---------------------------------------------------------------------------
#define APAD 40
#define BPAD 136
#define A_BYTES (128 * APAD * 2)          // 10240
#define B_BYTES (BK * BPAD * 2)           // 8704
#define S_AHI 0
#define S_BHI (A_BYTES)
#define S_BYTES (A_BYTES + B_BYTES)       // 18944
#define SMEM_G (3 * S_BYTES)              // 56832 -> 2 CTAs/SM

// ---------------------------------------------------------------------------
// PTX helpers
// ---------------------------------------------------------------------------
__device__ __forceinline__ uint32_t smem_u32(const void* p) {
    uint32_t a;
    asm("{ .reg .u64 t; cvta.to.shared.u64 t, %1; cvt.u32.u64 %0, t; }" : "=r"(a) : "l"(p));
    return a;
}
__device__ __forceinline__ void ldsm4(uint32_t* r, uint32_t addr) {
    asm volatile("ldmatrix.sync.aligned.m8n8.x4.shared.b16 {%0,%1,%2,%3}, [%4];"
                 : "=r"(r[0]), "=r"(r[1]), "=r"(r[2]), "=r"(r[3]) : "r"(addr));
}
__device__ __forceinline__ void ldsm4t(uint32_t* r, uint32_t addr) {
    asm volatile("ldmatrix.sync.aligned.m8n8.x4.trans.shared.b16 {%0,%1,%2,%3}, [%4];"
                 : "=r"(r[0]), "=r"(r[1]), "=r"(r[2]), "=r"(r[3]) : "r"(addr));
}
__device__ __forceinline__ void hmma_f16(float* d, const uint32_t* a, const uint32_t* b) {
    asm volatile("mma.sync.aligned.m16n8k16.row.col.f32.f16.f16.f32 "
                 "{%0,%1,%2,%3}, {%4,%5,%6,%7}, {%8,%9}, {%0,%1,%2,%3};"
                 : "+f"(d[0]), "+f"(d[1]), "+f"(d[2]), "+f"(d[3])
                 : "r"(a[0]), "r"(a[1]), "r"(a[2]), "r"(a[3]), "r"(b[0]), "r"(b[1]));
}
__device__ __forceinline__ void cp16(uint32_t dst, const void* src) {
    asm volatile("cp.async.cg.shared.global [%0], [%1], 16;" :: "r"(dst), "l"(src));
}
#define CP_COMMIT() asm volatile("cp.async.commit_group;" ::: "memory")
#define CP_WAIT1()  asm volatile("cp.async.wait_group 1;" ::: "memory")

// ---------------- prep ----------------
// adj row-normalize -> fp16
__global__ __launch_bounds__(192)
void adjprep_kernel(const float* __restrict__ adj) {
    int row = blockIdx.x;
    int t   = threadIdx.x;
    const float4 v = ((const float4*)(adj + (size_t)row * NDIM))[t];
    float s = v.x + v.y + v.z + v.w;
    __shared__ float ws[6];
    __shared__ float rsh;
#pragma unroll
    for (int o = 16; o > 0; o >>= 1) s += __shfl_down_sync(0xffffffffu, s, o);
    if ((t & 31) == 0) ws[t >> 5] = s;
    __syncthreads();
    if (t == 0) {
        float tot = ws[0] + ws[1] + ws[2] + ws[3] + ws[4] + ws[5];
        rsh = (tot == 0.f) ? 0.f : (1.f / tot);
    }
    __syncthreads();
    float r = rsh;
    size_t base = (size_t)row * NDIM + t * 4;
    ((__half2*)(g_Adj + base))[0] = __floats2half2_rn(v.x * r, v.y * r);
    ((__half2*)(g_Adj + base))[1] = __floats2half2_rn(v.z * r, v.w * r);
}

// X -> fp16 into g_XY columns [0, 768)
__global__ __launch_bounds__(256)
void xhalf_kernel(const float* __restrict__ X) {
    size_t i = ((size_t)blockIdx.x * 256 + threadIdx.x) * 4;
    float4 v = *(const float4*)(X + i);
    size_t row = i / NDIM, col = i % NDIM;
    __half* d = g_XY + row * SXY + col;
    ((__half2*)d)[0] = __floats2half2_rn(v.x, v.y);
    ((__half2*)d)[1] = __floats2half2_rn(v.z, v.w);
}

// W_l -> rows [0,768), W_l1 -> rows [768,1536) of g_Wcat
__global__ __launch_bounds__(256)
void wcat_kernel(const float* __restrict__ W_l, const float* __restrict__ W_l1) {
    size_t i = ((size_t)blockIdx.x * 256 + threadIdx.x) * 4;
    {
        float4 v = *(const float4*)(W_l + i);
        ((__half2*)(g_Wcat + i))[0] = __floats2half2_rn(v.x, v.y);
        ((__half2*)(g_Wcat + i))[1] = __floats2half2_rn(v.z, v.w);
    }
    {
        float4 v = *(const float4*)(W_l1 + i);
        __half* d = g_Wcat + (size_t)NDIM * NDIM + i;
        ((__half2*)d)[0] = __floats2half2_rn(v.x, v.y);
        ((__half2*)d)[1] = __floats2half2_rn(v.z, v.w);
    }
}

// ---------------------------------------------------------------------------
// aggx: Y = adj_n @ X (fp16) -> g_XY cols [768,1536).  R7 pipeline, 2 CTA/SM.
// grid (6, 6, 32)
// ---------------------------------------------------------------------------
__global__ __launch_bounds__(256, 2)
void aggx_kernel() {
    extern __shared__ char sm[];
    const uint32_t smb = smem_u32(sm);

    const int b  = blockIdx.z;
    const int nb = blockIdx.x * 128;
    const int mb = blockIdx.y * 128;
    const __half* A = g_Adj + (size_t)b * NDIM * NDIM;
    const __half* B = g_XY + (size_t)b * NDIM * SXY;      // X part (cols 0-767)

    const int tid  = threadIdx.x;
    const int lane = tid & 31;
    const int wid  = tid >> 5;
    const int wm   = wid >> 1;
    const int wn   = wid & 1;
    const int ar  = tid >> 1;
    const int ak  = (tid & 1) * 16;
    const int bkr = tid >> 3;
    const int bn  = (tid & 7) * 16;

    auto issue = [&](int kt) {
        const uint32_t st = smb + (kt % 3) * S_BYTES;
        const size_t asrc = (size_t)(mb + ar) * NDIM + kt * BK;
        const size_t bsrc = (size_t)(kt * BK + bkr) * SXY + nb;
#pragma unroll
        for (int c = 0; c < 2; c++) {
            int ko = ak + c * 8;
            cp16(st + S_AHI + (uint32_t)(ar * APAD + ko) * 2, A + asrc + ko);
            int no = bn + c * 8;
            cp16(st + S_BHI + (uint32_t)(bkr * BPAD + no) * 2, B + bsrc + no);
        }
        CP_COMMIT();
    };

    float acc[2][8][4];
#pragma unroll
    for (int i = 0; i < 2; i++)
#pragma unroll
        for (int j = 0; j < 8; j++)
#pragma unroll
            for (int q = 0; q < 4; q++) acc[i][j][q] = 0.f;

    issue(0);
    issue(1);

#pragma unroll 1
    for (int kt = 0; kt < NKT1; kt++) {
        CP_WAIT1();
        __syncthreads();
        if (kt + 2 < NKT1) issue(kt + 2); else CP_COMMIT();

        const uint32_t st = smb + (kt % 3) * S_BYTES;
#pragma unroll
        for (int ks = 0; ks < 2; ks++) {
            const int k0 = ks * 16;
            uint32_t a[2][4], bb[4][4];
#pragma unroll
            for (int m = 0; m < 2; m++)
                ldsm4(a[m], st + S_AHI + (uint32_t)((wm * 32 + m * 16 + (lane & 15)) * APAD
                                                    + k0 + (lane >> 4) * 8) * 2);
#pragma unroll
            for (int p = 0; p < 4; p++)
                ldsm4t(bb[p], st + S_BHI + (uint32_t)((k0 + (lane & 15)) * BPAD
                                                      + wn * 64 + p * 16 + (lane >> 4) * 8) * 2);
#pragma unroll
            for (int m = 0; m < 2; m++)
#pragma unroll
                for (int p = 0; p < 4; p++)
#pragma unroll
                    for (int h = 0; h < 2; h++)
                        hmma_f16(acc[m][p * 2 + h], a[m], &bb[p][h * 2]);
        }
    }

    // write Y (fp16) into g_XY columns 768+
    const int row0 = mb + wm * 32 + (lane >> 2);
    const int col0 = nb + wn * 64 + (lane & 3) * 2;
    __half* Yb = g_XY + (size_t)b * NDIM * SXY + NDIM;    // col offset 768
#pragma unroll
    for (int m = 0; m < 2; m++)
#pragma unroll
        for (int ns = 0; ns < 8; ns++) {
            __half* c0 = Yb + (size_t)(row0 + m * 16) * SXY + col0 + ns * 8;
            __half* c1 = c0 + 8 * SXY;
            *(__half2*)c0 = __floats2half2_rn(acc[m][ns][0], acc[m][ns][1]);
            *(__half2*)c1 = __floats2half2_rn(acc[m][ns][2], acc[m][ns][3]);
        }
}

// ---------------------------------------------------------------------------
// biggemm: out = lrelu( [X|Y] @ [W_l ; W_l1] ), K=1536 uniform fp16.
// grid (6, 192), 2 CTA/SM
// ---------------------------------------------------------------------------
__global__ __launch_bounds__(256, 2)
void biggemm_kernel(float* __restrict__ out) {
    extern __shared__ char sm[];
    const uint32_t smb = smem_u32(sm);

    const int nb = blockIdx.x * 128;
    const int mb = blockIdx.y * 128;
    const int tid  = threadIdx.x;
    const int lane = tid & 31;
    const int wid  = tid >> 5;
    const int wm   = wid >> 1;
    const int wn   = wid & 1;
    const int ar  = tid >> 1;
    const int ak  = (tid & 1) * 16;
    const int bkr = tid >> 3;
    const int bn  = (tid & 7) * 16;

    auto issue = [&](int kt) {
        const uint32_t st = smb + (kt % 3) * S_BYTES;
        const size_t asrc = (size_t)(mb + ar) * SXY + kt * BK;
        const size_t bsrc = (size_t)(kt * BK + bkr) * NDIM + nb;
#pragma unroll
        for (int c = 0; c < 2; c++) {
            int ko = ak + c * 8;
            cp16(st + S_AHI + (uint32_t)(ar * APAD + ko) * 2, g_XY + asrc + ko);
            int no = bn + c * 8;
            cp16(st + S_BHI + (uint32_t)(bkr * BPAD + no) * 2, g_Wcat + bsrc + no);
        }
        CP_COMMIT();
    };

    float acc[2][8][4];
#pragma unroll
    for (int i = 0; i < 2; i++)
#pragma unroll
        for (int j = 0; j < 8; j++)
#pragma unroll
            for (int q = 0; q < 4; q++) acc[i][j][q] = 0.f;

    issue(0);
    issue(1);

#pragma unroll 1
    for (int kt = 0; kt < NKT_T; kt++) {
        CP_WAIT1();
        __syncthreads();
        if (kt + 2 < NKT_T) issue(kt + 2); else CP_COMMIT();

        const uint32_t st = smb + (kt % 3) * S_BYTES;
#pragma unroll
        for (int ks = 0; ks < 2; ks++) {
            const int k0 = ks * 16;
            uint32_t a[2][4], bb[4][4];
#pragma unroll
            for (int m = 0; m < 2; m++)
                ldsm4(a[m], st + S_AHI + (uint32_t)((wm * 32 + m * 16 + (lane & 15)) * APAD
                                                    + k0 + (lane >> 4) * 8) * 2);
#pragma unroll
            for (int p = 0; p < 4; p++)
                ldsm4t(bb[p], st + S_BHI + (uint32_t)((k0 + (lane & 15)) * BPAD
                                                      + wn * 64 + p * 16 + (lane >> 4) * 8) * 2);
#pragma unroll
            for (int m = 0; m < 2; m++)
#pragma unroll
                for (int p = 0; p < 4; p++)
#pragma unroll
                    for (int h = 0; h < 2; h++)
                        hmma_f16(acc[m][p * 2 + h], a[m], &bb[p][h * 2]);
        }
    }

    const int row0 = mb + wm * 32 + (lane >> 2);
    const int col0 = nb + wn * 64 + (lane & 3) * 2;
#pragma unroll
    for (int m = 0; m < 2; m++)
#pragma unroll
        for (int ns = 0; ns < 8; ns++) {
            float h0 = acc[m][ns][0], h1 = acc[m][ns][1];
            float h2 = acc[m][ns][2], h3 = acc[m][ns][3];
            h0 = (h0 > 0.f) ? h0 : 0.01f * h0;
            h1 = (h1 > 0.f) ? h1 : 0.01f * h1;
            h2 = (h2 > 0.f) ? h2 : 0.01f * h2;
            h3 = (h3 > 0.f) ? h3 : 0.01f * h3;
            float* c0 = out + (size_t)(row0 + m * 16) * NDIM + col0 + ns * 8;
            float* c1 = c0 + 8 * NDIM;
            *(float2*)c0 = make_float2(h0, h1);
            *(float2*)c1 = make_float2(h2, h3);
        }
}

// ---------------------------------------------------------------------------
extern "C" void kernel_launch(void* const* d_in, const int* in_sizes, int n_in,
                              void* d_out, int out_size)
{
    const float* X    = (const float*)d_in[0];
    const float* adj  = (const float*)d_in[1];
    const float* W_l  = (const float*)d_in[2];
    const float* W_l1 = (const float*)d_in[3];
    float* out = (float*)d_out;

    cudaFuncSetAttribute(aggx_kernel,    cudaFuncAttributeMaxDynamicSharedMemorySize, SMEM_G);
    cudaFuncSetAttribute(biggemm_kernel, cudaFuncAttributeMaxDynamicSharedMemorySize, SMEM_G);

    adjprep_kernel<<<MTOT, 192>>>(adj);
    xhalf_kernel<<<(MTOT * NDIM) / 1024, 256>>>(X);
    wcat_kernel<<<(NDIM * NDIM) / 1024, 256>>>(W_l, W_l1);

    aggx_kernel<<<dim3(6, 6, 32), 256, SMEM_G>>>();
    biggemm_kernel<<<dim3(6, 192), 256, SMEM_G>>>(out);
}